// round 13
// baseline (speedup 1.0000x reference)
#include <cuda_runtime.h>
#include <cstdint>
#include <cstddef>

#define Lq 2048
#define Hh 16
#define Cc 64
#define Bb 2

// Output layout: [context (B,L,H*C)] [scores (B,H,L,L)] [weights (B,H,L,L)]
#define OFF_S  ((size_t)Bb * Lq * Hh * Cc)
#define NSCORE ((size_t)Bb * Hh * Lq * Lq)
#define OFF_W  (OFF_S + NSCORE)

// scores: av-style pipeline. Q[64][68] staged once; stages = K[32][68] + E[64][36]
#define SJ 32
#define KROW 68
#define EROW 36
#define SC_STAGE (SJ * KROW + 64 * EROW)          // 4480 floats
#define SC_STAGES 4
#define SMEM_SC ((64 * KROW + SC_STAGES * SC_STAGE) * 4)   // 89088 B

// av: 4-stage cp.async pipeline, 32-wide j chunks (proven)
#define AVJ 32
#define WROW 36
#define VROW 72
#define AV_STAGE (64 * WROW + AVJ * VROW)         // 4608 floats
#define AV_STAGES 4
#define SMEM_AV (AV_STAGES * AV_STAGE * 4)        // 73728 B

// ---------------------------------------------------------------------------
__device__ __forceinline__ float f2tf(float x) {
    unsigned r;
    asm("cvt.rna.tf32.f32 %0, %1;" : "=r"(r) : "f"(x));
    return __uint_as_float(r);
}

__device__ __forceinline__ void mma_tf32(float (&d)[4], const float (&a)[4],
                                         float b0, float b1) {
    asm volatile(
        "mma.sync.aligned.m16n8k8.row.col.f32.tf32.tf32.f32 "
        "{%0,%1,%2,%3}, {%4,%5,%6,%7}, {%8,%9}, {%0,%1,%2,%3};"
        : "+f"(d[0]), "+f"(d[1]), "+f"(d[2]), "+f"(d[3])
        : "r"(__float_as_uint(a[0])), "r"(__float_as_uint(a[1])),
          "r"(__float_as_uint(a[2])), "r"(__float_as_uint(a[3])),
          "r"(__float_as_uint(b0)), "r"(__float_as_uint(b1)));
}

__device__ __forceinline__ void cp16(void* s, const void* g) {
    const unsigned saddr = (unsigned)__cvta_generic_to_shared(s);
    asm volatile("cp.async.cg.shared.global [%0], [%1], 16;"
                 :: "r"(saddr), "l"(g));
}

// ---------------------------------------------------------------------------
// Kernel 1: scores = QK^T + edge. CTA = 64 i-rows of one (b,h); j-loop of
// 32-wide chunks, K + edge both staged via 4-stage cp.async pipeline.
// 8 warps as 4(i) x 2(j): warp = 16i x 16j per chunk.
// ---------------------------------------------------------------------------
__global__ __launch_bounds__(256, 2) void scores_kernel(
    const float* __restrict__ q, const float* __restrict__ k,
    const float* __restrict__ edge, float* __restrict__ out_scores) {
    extern __shared__ float sm[];
    float* Qs = sm;                       // [64][KROW]

    const int h = blockIdx.y >> 1;
    const int b = blockIdx.y & 1;
    const int bh = b * Hh + h;
    const int i0 = blockIdx.x << 6;
    const int tid = threadIdx.x;
    const int warp = tid >> 5, lane = tid & 31;
    const int wi = warp >> 1, wj = warp & 1;
    const int ibase = wi * 16, jbase = wj * 16;
    const int gid = lane >> 2, qid = lane & 3;

    auto issue = [&](int jt, int s) {
        float* Kc = sm + 64 * KROW + s * SC_STAGE;
        float* Ec = Kc + SJ * KROW;
        const int j0 = jt * SJ;
#pragma unroll
        for (int t = 0; t < 2; t++) {         // K chunk: 32 rows x 64 c
            const int idx = t * 256 + tid;
            const int row = idx >> 4;
            const int c4 = (idx & 15) * 4;
            cp16(&Kc[row * KROW + c4],
                 k + ((size_t)(b * Lq + j0 + row) * Hh + h) * Cc + c4);
        }
#pragma unroll
        for (int t = 0; t < 2; t++) {         // edge chunk: 64 rows x 32 j
            const int idx = t * 256 + tid;
            const int row = idx >> 3;
            const int c4 = (idx & 7) * 4;
            cp16(&Ec[row * EROW + c4],
                 edge + ((size_t)h * Lq + i0 + row) * Lq + j0 + c4);
        }
        asm volatile("cp.async.commit_group;");
    };

    issue(0, 0);
    issue(1, 1);
    issue(2, 2);

    // Stage Q once (tf32-converted), overlapped with in-flight cp.async.
#pragma unroll
    for (int t = 0; t < 4; t++) {
        const int idx = t * 256 + tid;
        const int row = idx >> 4;
        const int c4 = (idx & 15) * 4;
        const float4 vq = *(const float4*)(q +
            ((size_t)(b * Lq + i0 + row) * Hh + h) * Cc + c4);
        float* dq = &Qs[row * KROW + c4];
        dq[0] = f2tf(vq.x); dq[1] = f2tf(vq.y);
        dq[2] = f2tf(vq.z); dq[3] = f2tf(vq.w);
    }
    __syncthreads();

    const int NT = Lq / SJ;   // 64

    for (int jt = 0; jt < NT; jt++) {
        asm volatile("cp.async.wait_group 2;");
        __syncthreads();
        if (jt + 3 < NT) {
            issue(jt + 3, (jt + 3) & 3);
        } else {
            asm volatile("cp.async.commit_group;");
        }

        const float* Kc = sm + 64 * KROW + (jt & 3) * SC_STAGE;
        const float* Ec = Kc + SJ * KROW;
        const int j0 = jt * SJ;

        float acc[2][4] = {};
#pragma unroll
        for (int kk = 0; kk < 8; kk++) {
            const int k0 = kk * 8;
            float a[4];
            const int rr = ibase + gid;
            a[0] = Qs[rr * KROW + k0 + qid];
            a[1] = Qs[(rr + 8) * KROW + k0 + qid];
            a[2] = Qs[rr * KROW + k0 + qid + 4];
            a[3] = Qs[(rr + 8) * KROW + k0 + qid + 4];
#pragma unroll
            for (int n = 0; n < 2; n++) {
                const int cc = jbase + n * 8 + gid;
                const float b0 = f2tf(Kc[cc * KROW + k0 + qid]);
                const float b1 = f2tf(Kc[cc * KROW + k0 + qid + 4]);
                mma_tf32(acc[n], a, b0, b1);
            }
        }

        // Epilogue: edge from smem (pipelined), scores out (streaming).
#pragma unroll
        for (int n = 0; n < 2; n++) {
            const int col = jbase + n * 8 + 2 * qid;
            const int r0 = ibase + gid;
            const float2 e0 = *(const float2*)&Ec[r0 * EROW + col];
            const float2 e1 = *(const float2*)&Ec[(r0 + 8) * EROW + col];
            float2 o0, o1;
            o0.x = acc[n][0] + e0.x; o0.y = acc[n][1] + e0.y;
            o1.x = acc[n][2] + e1.x; o1.y = acc[n][3] + e1.y;
            __stcs((float2*)(out_scores +
                ((size_t)bh * Lq + i0 + r0) * Lq + j0 + col), o0);
            __stcs((float2*)(out_scores +
                ((size_t)bh * Lq + i0 + r0 + 8) * Lq + j0 + col), o1);
        }
    }
}

// ---------------------------------------------------------------------------
// Kernel 2: masked softmax. Block index = i*32 + bh (mask L2 reuse).
// Mask dtype classified inline from the first 1KB (two barrier-ANDs).
// ---------------------------------------------------------------------------
__global__ __launch_bounds__(256) void softmax_kernel(
    const float* __restrict__ scores, const void* __restrict__ mask,
    float* __restrict__ wout) {
    const int bh = blockIdx.x & 31;
    const int i  = blockIdx.x >> 5;
    const int b  = bh >> 4;
    const size_t soff = ((size_t)bh * Lq + i) * Lq;
    const size_t moff = ((size_t)(b * Lq + i)) * Lq;
    const int tid = threadIdx.x;

    const unsigned int mv = ((const unsigned int*)mask)[tid];
    const int all_i32 = __syncthreads_and(mv <= 1u);
    const int all_f32 = __syncthreads_and(mv == 0u || mv == 0x3F800000u);
    const int kind = all_i32 ? 1 : (all_f32 ? 2 : 0);

    const float4* sp = (const float4*)(scores + soff);
    const float4 s0 = __ldcs(sp + tid);
    const float4 s1 = __ldcs(sp + 256 + tid);

    float mb[8];
    if (kind == 1) {
        const int4* mp = (const int4*)((const int*)mask + moff);
        const int4 m0 = mp[tid], m1 = mp[256 + tid];
        mb[0] = m0.x ? 1.f : 0.f; mb[1] = m0.y ? 1.f : 0.f;
        mb[2] = m0.z ? 1.f : 0.f; mb[3] = m0.w ? 1.f : 0.f;
        mb[4] = m1.x ? 1.f : 0.f; mb[5] = m1.y ? 1.f : 0.f;
        mb[6] = m1.z ? 1.f : 0.f; mb[7] = m1.w ? 1.f : 0.f;
    } else if (kind == 2) {
        const float4* mp = (const float4*)((const float*)mask + moff);
        const float4 m0 = mp[tid], m1 = mp[256 + tid];
        mb[0] = (m0.x != 0.f); mb[1] = (m0.y != 0.f);
        mb[2] = (m0.z != 0.f); mb[3] = (m0.w != 0.f);
        mb[4] = (m1.x != 0.f); mb[5] = (m1.y != 0.f);
        mb[6] = (m1.z != 0.f); mb[7] = (m1.w != 0.f);
    } else {
        const uchar4* mp = (const uchar4*)((const unsigned char*)mask + moff);
        const uchar4 m0 = mp[tid], m1 = mp[256 + tid];
        mb[0] = m0.x ? 1.f : 0.f; mb[1] = m0.y ? 1.f : 0.f;
        mb[2] = m0.z ? 1.f : 0.f; mb[3] = m0.w ? 1.f : 0.f;
        mb[4] = m1.x ? 1.f : 0.f; mb[5] = m1.y ? 1.f : 0.f;
        mb[6] = m1.z ? 1.f : 0.f; mb[7] = m1.w ? 1.f : 0.f;
    }

    const float sv[8] = {s0.x, s0.y, s0.z, s0.w, s1.x, s1.y, s1.z, s1.w};
    float x[8];
#pragma unroll
    for (int t = 0; t < 8; t++)
        x[t] = (mb[t] != 0.f) ? sv[t] * 0.125f : -1e18f;

    float mx = x[0];
#pragma unroll
    for (int t = 1; t < 8; t++) mx = fmaxf(mx, x[t]);
#pragma unroll
    for (int o = 16; o; o >>= 1) mx = fmaxf(mx, __shfl_xor_sync(0xffffffffu, mx, o));

    __shared__ float red_max[8];
    __shared__ float red_sum[8];
    if ((tid & 31) == 0) red_max[tid >> 5] = mx;
    __syncthreads();
    mx = red_max[0];
#pragma unroll
    for (int wi = 1; wi < 8; wi++) mx = fmaxf(mx, red_max[wi]);

    float e[8];
    float s = 0.0f;
#pragma unroll
    for (int t = 0; t < 8; t++) {
        e[t] = __expf(x[t] - mx);
        s += e[t];
    }
#pragma unroll
    for (int o = 16; o; o >>= 1) s += __shfl_xor_sync(0xffffffffu, s, o);
    if ((tid & 31) == 0) red_sum[tid >> 5] = s;
    __syncthreads();
    s = red_sum[0];
#pragma unroll
    for (int wi = 1; wi < 8; wi++) s += red_sum[wi];

    const float inv = 1.0f / s;
    float4 w0, w1;
    w0.x = e[0] * inv * mb[0]; w0.y = e[1] * inv * mb[1];
    w0.z = e[2] * inv * mb[2]; w0.w = e[3] * inv * mb[3];
    w1.x = e[4] * inv * mb[4]; w1.y = e[5] * inv * mb[5];
    w1.z = e[6] * inv * mb[6]; w1.w = e[7] * inv * mb[7];
    float4* wp = (float4*)(wout + soff);
    __stcs(wp + tid, w0);
    __stcs(wp + 256 + tid, w1);
}

// ---------------------------------------------------------------------------
// Kernel 3: ctx = W * V. CTA 64(i) x 64(c), j chunks of 32.
// 4-stage cp.async pipeline, one syncthreads/iter, rna tf32 on fragments.
// (Byte-identical to R9 — proven 173us.)
// ---------------------------------------------------------------------------
__global__ __launch_bounds__(256, 3) void av_kernel(
    const float* __restrict__ w, const float* __restrict__ v,
    float* __restrict__ ctx) {
    extern __shared__ float sm[];

    const int bh = blockIdx.y;
    const int b = bh >> 4, h = bh & 15;
    const int i0 = blockIdx.x << 6;
    const int tid = threadIdx.x;
    const int warp = tid >> 5, lane = tid & 31;
    const int wi = warp >> 1, wc = warp & 1;
    const int ibase = wi * 16, cbase = wc * 32;
    const int gid = lane >> 2, qid = lane & 3;

    const int wrow = tid >> 3;
    const int wc4  = (tid & 7) * 4;
    const int vrow = tid >> 4;
    const int vc4  = (tid & 15) * 4;

    auto issue = [&](int jt, int s) {
        float* Wb = sm + s * AV_STAGE;
        float* Vb = Wb + 64 * WROW;
        const int j0 = jt * AVJ;
#pragma unroll
        for (int t = 0; t < 2; t++) {
            const int row = t * 32 + wrow;
            cp16(&Wb[row * WROW + wc4],
                 w + ((size_t)bh * Lq + i0 + row) * Lq + j0 + wc4);
        }
#pragma unroll
        for (int t = 0; t < 2; t++) {
            const int row = t * 16 + vrow;
            cp16(&Vb[row * VROW + vc4],
                 v + ((size_t)(b * Lq + j0 + row) * Hh + h) * Cc + vc4);
        }
        asm volatile("cp.async.commit_group;");
    };

    float acc[4][4] = {};

    const int NT = Lq / AVJ;   // 64
    issue(0, 0);
    issue(1, 1);
    issue(2, 2);

    for (int jt = 0; jt < NT; jt++) {
        asm volatile("cp.async.wait_group 2;");
        __syncthreads();
        if (jt + 3 < NT) {
            issue(jt + 3, (jt + 3) & 3);
        } else {
            asm volatile("cp.async.commit_group;");
        }

        const float* Wb = sm + (jt & 3) * AV_STAGE;
        const float* Vb = Wb + 64 * WROW;

#pragma unroll
        for (int kk = 0; kk < 4; kk++) {
            const int k0 = kk * 8;
            float a[4];
            const int rr = ibase + gid;
            a[0] = f2tf(Wb[rr * WROW + k0 + qid]);
            a[1] = f2tf(Wb[(rr + 8) * WROW + k0 + qid]);
            a[2] = f2tf(Wb[rr * WROW + k0 + qid + 4]);
            a[3] = f2tf(Wb[(rr + 8) * WROW + k0 + qid + 4]);
#pragma unroll
            for (int n = 0; n < 4; n++) {
                const int cc = cbase + n * 8 + gid;
                const float b0 = f2tf(Vb[(k0 + qid) * VROW + cc]);
                const float b1 = f2tf(Vb[(k0 + qid + 4) * VROW + cc]);
                mma_tf32(acc[n], a, b0, b1);
            }
        }
    }

#pragma unroll
    for (int n = 0; n < 4; n++) {
        const int i = i0 + ibase + gid;
        const int c = h * Cc + cbase + n * 8 + 2 * qid;
        float2 oa, ob;
        oa.x = acc[n][0]; oa.y = acc[n][1];
        ob.x = acc[n][2]; ob.y = acc[n][3];
        *(float2*)(ctx + ((size_t)(b * Lq + i)) * (Hh * Cc) + c) = oa;
        *(float2*)(ctx + ((size_t)(b * Lq + i + 8)) * (Hh * Cc) + c) = ob;
    }
}

// ---------------------------------------------------------------------------
extern "C" void kernel_launch(void* const* d_in, const int* in_sizes, int n_in,
                              void* d_out, int out_size) {
    (void)in_sizes; (void)n_in; (void)out_size;
    const float* q    = (const float*)d_in[0];
    const float* k    = (const float*)d_in[1];
    const float* v    = (const float*)d_in[2];
    const void*  mask = d_in[3];
    const float* edge = (const float*)d_in[4];

    float* out     = (float*)d_out;
    float* ctx     = out;
    float* scores  = out + OFF_S;
    float* weights = out + OFF_W;

    cudaFuncSetAttribute(scores_kernel,
        cudaFuncAttributeMaxDynamicSharedMemorySize, SMEM_SC);
    cudaFuncSetAttribute(av_kernel,
        cudaFuncAttributeMaxDynamicSharedMemorySize, SMEM_AV);

    {
        dim3 grid(Lq / 64, Bb * Hh);
        scores_kernel<<<grid, 256, SMEM_SC>>>(q, k, edge, scores);
    }
    {
        softmax_kernel<<<Bb * Hh * Lq, 256>>>(scores, mask, weights);
    }
    {
        dim3 grid(Lq / 64, Bb * Hh);
        av_kernel<<<grid, 256, SMEM_AV>>>(weights, v, ctx);
    }
}

// round 14
// speedup vs baseline: 1.0816x; 1.0816x over previous
#include <cuda_runtime.h>
#include <cstdint>
#include <cstddef>

#define Lq 2048
#define Hh 16
#define Cc 64
#define Bb 2

// Output layout: [context (B,L,H*C)] [scores (B,H,L,L)] [weights (B,H,L,L)]
#define OFF_S  ((size_t)Bb * Lq * Hh * Cc)
#define NSCORE ((size_t)Bb * Hh * Lq * Lq)
#define OFF_W  (OFF_S + NSCORE)

#define PADA 68
#define SMEM_SCORES (2 * 128 * PADA * 4)          // Qs + Ks = 69632 B

// av: 3-stage cp.async pipeline (55.3 KB -> 4 CTAs/SM), 32-wide j chunks
#define AVJ 32
#define WROW 36
#define VROW 72
#define AV_STAGE (64 * WROW + AVJ * VROW)         // 4608 floats
#define AV_STAGES 3
#define SMEM_AV (AV_STAGES * AV_STAGE * 4)        // 55296 B

// ---------------------------------------------------------------------------
__device__ __forceinline__ float f2tf(float x) {
    unsigned r;
    asm("cvt.rna.tf32.f32 %0, %1;" : "=r"(r) : "f"(x));
    return __uint_as_float(r);
}

__device__ __forceinline__ void mma_tf32(float (&d)[4], const float (&a)[4],
                                         float b0, float b1) {
    asm volatile(
        "mma.sync.aligned.m16n8k8.row.col.f32.tf32.tf32.f32 "
        "{%0,%1,%2,%3}, {%4,%5,%6,%7}, {%8,%9}, {%0,%1,%2,%3};"
        : "+f"(d[0]), "+f"(d[1]), "+f"(d[2]), "+f"(d[3])
        : "r"(__float_as_uint(a[0])), "r"(__float_as_uint(a[1])),
          "r"(__float_as_uint(a[2])), "r"(__float_as_uint(a[3])),
          "r"(__float_as_uint(b0)), "r"(__float_as_uint(b1)));
}

__device__ __forceinline__ void cp16(void* s, const void* g) {
    const unsigned saddr = (unsigned)__cvta_generic_to_shared(s);
    asm volatile("cp.async.cg.shared.global [%0], [%1], 16;"
                 :: "r"(saddr), "l"(g));
}

// ---------------------------------------------------------------------------
// Kernel 1 (R9 verbatim): scores = QK^T + edge. 128x128 tile, K=64 one pass.
// grid.x = jb*2 + b (edge L2 reuse across batches).
// ---------------------------------------------------------------------------
__global__ __launch_bounds__(256) void scores_kernel(
    const float* __restrict__ q, const float* __restrict__ k,
    const float* __restrict__ edge, float* __restrict__ out_scores) {
    extern __shared__ float sm[];
    float* Qs = sm;                 // [128][PADA] : [i][c]
    float* Ks = sm + 128 * PADA;    // [128][PADA] : [j][c]

    const int h = blockIdx.z;
    const int b = blockIdx.x & 1;
    const int jb = blockIdx.x >> 1;
    const int bh = b * Hh + h;
    const int i0 = blockIdx.y << 7;
    const int j0 = jb << 7;
    const int tid = threadIdx.x;

#pragma unroll
    for (int r = 0; r < 8; r++) {
        const int idx = r * 256 + tid;
        const int row = idx >> 4;
        const int c4 = (idx & 15) * 4;
        const float4 vq = *(const float4*)(q +
            ((size_t)(b * Lq + i0 + row) * Hh + h) * Cc + c4);
        float* dq = &Qs[row * PADA + c4];
        dq[0] = f2tf(vq.x); dq[1] = f2tf(vq.y);
        dq[2] = f2tf(vq.z); dq[3] = f2tf(vq.w);
        const float4 vk = *(const float4*)(k +
            ((size_t)(b * Lq + j0 + row) * Hh + h) * Cc + c4);
        float* dk = &Ks[row * PADA + c4];
        dk[0] = f2tf(vk.x); dk[1] = f2tf(vk.y);
        dk[2] = f2tf(vk.z); dk[3] = f2tf(vk.w);
    }
    __syncthreads();

    const int warp = tid >> 5, lane = tid & 31;
    const int wi = warp >> 1, wj = warp & 1;
    const int ibase = wi * 32, jbase = wj * 64;
    const int gid = lane >> 2, qid = lane & 3;

    float acc[2][8][4] = {};

#pragma unroll
    for (int kk = 0; kk < 8; kk++) {
        const int k0 = kk * 8;
        float a[2][4];
#pragma unroll
        for (int m = 0; m < 2; m++) {
            const int rr = ibase + m * 16 + gid;
            a[m][0] = Qs[rr * PADA + k0 + qid];
            a[m][1] = Qs[(rr + 8) * PADA + k0 + qid];
            a[m][2] = Qs[rr * PADA + k0 + qid + 4];
            a[m][3] = Qs[(rr + 8) * PADA + k0 + qid + 4];
        }
#pragma unroll
        for (int n = 0; n < 8; n++) {
            const int cc = jbase + n * 8 + gid;
            const float b0 = Ks[cc * PADA + k0 + qid];
            const float b1 = Ks[cc * PADA + k0 + qid + 4];
            mma_tf32(acc[0][n], a[0], b0, b1);
            mma_tf32(acc[1][n], a[1], b0, b1);
        }
    }

#pragma unroll
    for (int m = 0; m < 2; m++) {
#pragma unroll
        for (int n = 0; n < 8; n++) {
            const int i = i0 + ibase + m * 16 + gid;
            const int j = j0 + jbase + n * 8 + 2 * qid;
            const size_t e0 = ((size_t)h * Lq + i) * Lq + j;
            const size_t s0 = ((size_t)bh * Lq + i) * Lq + j;
            const float2 ea = *(const float2*)(edge + e0);
            const float2 eb = *(const float2*)(edge + e0 + 8 * (size_t)Lq);
            float2 oa, ob;
            oa.x = acc[m][n][0] + ea.x; oa.y = acc[m][n][1] + ea.y;
            ob.x = acc[m][n][2] + eb.x; ob.y = acc[m][n][3] + eb.y;
            __stcs((float2*)(out_scores + s0), oa);
            __stcs((float2*)(out_scores + s0 + 8 * (size_t)Lq), ob);
        }
    }
}

// ---------------------------------------------------------------------------
// Kernel 2 (R11 verbatim): masked softmax. Block index = i*32 + bh.
// Mask dtype classified inline from the first 1KB (two barrier-ANDs).
// ---------------------------------------------------------------------------
__global__ __launch_bounds__(256) void softmax_kernel(
    const float* __restrict__ scores, const void* __restrict__ mask,
    float* __restrict__ wout) {
    const int bh = blockIdx.x & 31;
    const int i  = blockIdx.x >> 5;
    const int b  = bh >> 4;
    const size_t soff = ((size_t)bh * Lq + i) * Lq;
    const size_t moff = ((size_t)(b * Lq + i)) * Lq;
    const int tid = threadIdx.x;

    const unsigned int mv = ((const unsigned int*)mask)[tid];
    const int all_i32 = __syncthreads_and(mv <= 1u);
    const int all_f32 = __syncthreads_and(mv == 0u || mv == 0x3F800000u);
    const int kind = all_i32 ? 1 : (all_f32 ? 2 : 0);

    const float4* sp = (const float4*)(scores + soff);
    const float4 s0 = __ldcs(sp + tid);
    const float4 s1 = __ldcs(sp + 256 + tid);

    float mb[8];
    if (kind == 1) {
        const int4* mp = (const int4*)((const int*)mask + moff);
        const int4 m0 = mp[tid], m1 = mp[256 + tid];
        mb[0] = m0.x ? 1.f : 0.f; mb[1] = m0.y ? 1.f : 0.f;
        mb[2] = m0.z ? 1.f : 0.f; mb[3] = m0.w ? 1.f : 0.f;
        mb[4] = m1.x ? 1.f : 0.f; mb[5] = m1.y ? 1.f : 0.f;
        mb[6] = m1.z ? 1.f : 0.f; mb[7] = m1.w ? 1.f : 0.f;
    } else if (kind == 2) {
        const float4* mp = (const float4*)((const float*)mask + moff);
        const float4 m0 = mp[tid], m1 = mp[256 + tid];
        mb[0] = (m0.x != 0.f); mb[1] = (m0.y != 0.f);
        mb[2] = (m0.z != 0.f); mb[3] = (m0.w != 0.f);
        mb[4] = (m1.x != 0.f); mb[5] = (m1.y != 0.f);
        mb[6] = (m1.z != 0.f); mb[7] = (m1.w != 0.f);
    } else {
        const uchar4* mp = (const uchar4*)((const unsigned char*)mask + moff);
        const uchar4 m0 = mp[tid], m1 = mp[256 + tid];
        mb[0] = m0.x ? 1.f : 0.f; mb[1] = m0.y ? 1.f : 0.f;
        mb[2] = m0.z ? 1.f : 0.f; mb[3] = m0.w ? 1.f : 0.f;
        mb[4] = m1.x ? 1.f : 0.f; mb[5] = m1.y ? 1.f : 0.f;
        mb[6] = m1.z ? 1.f : 0.f; mb[7] = m1.w ? 1.f : 0.f;
    }

    const float sv[8] = {s0.x, s0.y, s0.z, s0.w, s1.x, s1.y, s1.z, s1.w};
    float x[8];
#pragma unroll
    for (int t = 0; t < 8; t++)
        x[t] = (mb[t] != 0.f) ? sv[t] * 0.125f : -1e18f;

    float mx = x[0];
#pragma unroll
    for (int t = 1; t < 8; t++) mx = fmaxf(mx, x[t]);
#pragma unroll
    for (int o = 16; o; o >>= 1) mx = fmaxf(mx, __shfl_xor_sync(0xffffffffu, mx, o));

    __shared__ float red_max[8];
    __shared__ float red_sum[8];
    if ((tid & 31) == 0) red_max[tid >> 5] = mx;
    __syncthreads();
    mx = red_max[0];
#pragma unroll
    for (int wi = 1; wi < 8; wi++) mx = fmaxf(mx, red_max[wi]);

    float e[8];
    float s = 0.0f;
#pragma unroll
    for (int t = 0; t < 8; t++) {
        e[t] = __expf(x[t] - mx);
        s += e[t];
    }
#pragma unroll
    for (int o = 16; o; o >>= 1) s += __shfl_xor_sync(0xffffffffu, s, o);
    if ((tid & 31) == 0) red_sum[tid >> 5] = s;
    __syncthreads();
    s = red_sum[0];
#pragma unroll
    for (int wi = 1; wi < 8; wi++) s += red_sum[wi];

    const float inv = 1.0f / s;
    float4 w0, w1;
    w0.x = e[0] * inv * mb[0]; w0.y = e[1] * inv * mb[1];
    w0.z = e[2] * inv * mb[2]; w0.w = e[3] * inv * mb[3];
    w1.x = e[4] * inv * mb[4]; w1.y = e[5] * inv * mb[5];
    w1.z = e[6] * inv * mb[6]; w1.w = e[7] * inv * mb[7];
    float4* wp = (float4*)(wout + soff);
    __stcs(wp + tid, w0);
    __stcs(wp + 256 + tid, w1);
}

// ---------------------------------------------------------------------------
// Kernel 3: ctx = W * V. CTA 64(i) x 64(c), j chunks of 32.
// 3-stage cp.async pipeline (issue-ahead 2), 4 CTAs/SM, rna tf32 fragments.
// ---------------------------------------------------------------------------
__global__ __launch_bounds__(256, 4) void av_kernel(
    const float* __restrict__ w, const float* __restrict__ v,
    float* __restrict__ ctx) {
    extern __shared__ float sm[];

    const int bh = blockIdx.y;
    const int b = bh >> 4, h = bh & 15;
    const int i0 = blockIdx.x << 6;
    const int tid = threadIdx.x;
    const int warp = tid >> 5, lane = tid & 31;
    const int wi = warp >> 1, wc = warp & 1;
    const int ibase = wi * 16, cbase = wc * 32;
    const int gid = lane >> 2, qid = lane & 3;

    const int wrow = tid >> 3;
    const int wc4  = (tid & 7) * 4;
    const int vrow = tid >> 4;
    const int vc4  = (tid & 15) * 4;

    auto issue = [&](int jt, int s) {
        float* Wb = sm + s * AV_STAGE;
        float* Vb = Wb + 64 * WROW;
        const int j0 = jt * AVJ;
#pragma unroll
        for (int t = 0; t < 2; t++) {
            const int row = t * 32 + wrow;
            cp16(&Wb[row * WROW + wc4],
                 w + ((size_t)bh * Lq + i0 + row) * Lq + j0 + wc4);
        }
#pragma unroll
        for (int t = 0; t < 2; t++) {
            const int row = t * 16 + vrow;
            cp16(&Vb[row * VROW + vc4],
                 v + ((size_t)(b * Lq + j0 + row) * Hh + h) * Cc + vc4);
        }
        asm volatile("cp.async.commit_group;");
    };

    float acc[4][4] = {};

    const int NT = Lq / AVJ;   // 64
    issue(0, 0);
    issue(1, 1);

    int sidx = 0;   // buffer of jt
    for (int jt = 0; jt < NT; jt++) {
        asm volatile("cp.async.wait_group 1;");
        __syncthreads();
        if (jt + 2 < NT) {
            int nb = sidx + 2; if (nb >= 3) nb -= 3;
            issue(jt + 2, nb);
        } else {
            asm volatile("cp.async.commit_group;");
        }

        const float* Wb = sm + sidx * AV_STAGE;
        const float* Vb = Wb + 64 * WROW;

#pragma unroll
        for (int kk = 0; kk < 4; kk++) {
            const int k0 = kk * 8;
            float a[4];
            const int rr = ibase + gid;
            a[0] = f2tf(Wb[rr * WROW + k0 + qid]);
            a[1] = f2tf(Wb[(rr + 8) * WROW + k0 + qid]);
            a[2] = f2tf(Wb[rr * WROW + k0 + qid + 4]);
            a[3] = f2tf(Wb[(rr + 8) * WROW + k0 + qid + 4]);
#pragma unroll
            for (int n = 0; n < 4; n++) {
                const int cc = cbase + n * 8 + gid;
                const float b0 = f2tf(Vb[(k0 + qid) * VROW + cc]);
                const float b1 = f2tf(Vb[(k0 + qid + 4) * VROW + cc]);
                mma_tf32(acc[n], a, b0, b1);
            }
        }
        if (++sidx == 3) sidx = 0;
    }

#pragma unroll
    for (int n = 0; n < 4; n++) {
        const int i = i0 + ibase + gid;
        const int c = h * Cc + cbase + n * 8 + 2 * qid;
        float2 oa, ob;
        oa.x = acc[n][0]; oa.y = acc[n][1];
        ob.x = acc[n][2]; ob.y = acc[n][3];
        *(float2*)(ctx + ((size_t)(b * Lq + i)) * (Hh * Cc) + c) = oa;
        *(float2*)(ctx + ((size_t)(b * Lq + i + 8)) * (Hh * Cc) + c) = ob;
    }
}

// ---------------------------------------------------------------------------
extern "C" void kernel_launch(void* const* d_in, const int* in_sizes, int n_in,
                              void* d_out, int out_size) {
    (void)in_sizes; (void)n_in; (void)out_size;
    const float* q    = (const float*)d_in[0];
    const float* k    = (const float*)d_in[1];
    const float* v    = (const float*)d_in[2];
    const void*  mask = d_in[3];
    const float* edge = (const float*)d_in[4];

    float* out     = (float*)d_out;
    float* ctx     = out;
    float* scores  = out + OFF_S;
    float* weights = out + OFF_W;

    cudaFuncSetAttribute(scores_kernel,
        cudaFuncAttributeMaxDynamicSharedMemorySize, SMEM_SCORES);
    cudaFuncSetAttribute(av_kernel,
        cudaFuncAttributeMaxDynamicSharedMemorySize, SMEM_AV);

    {
        dim3 grid(2 * (Lq / 128), Lq / 128, Hh);
        scores_kernel<<<grid, 256, SMEM_SCORES>>>(q, k, edge, scores);
    }
    {
        softmax_kernel<<<Bb * Hh * Lq, 256>>>(scores, mask, weights);
    }
    {
        dim3 grid(Lq / 64, Bb * Hh);
        av_kernel<<<grid, 256, SMEM_AV>>>(weights, v, ctx);
    }
}